// round 1
// baseline (speedup 1.0000x reference)
#include <cuda_runtime.h>

#define TOT 8192
#define BN 16
#define C 64
#define K 20
#define CN 512
#define NW (BN*CN)
#define STEPS 8
#define BN_EPS 1e-5f

// ---- device scratch (no allocations allowed) ----
__device__ float g_xT[(size_t)BN*TOT*C];   // x transposed to (b, node, ch)  ~32MB
__device__ float g_curf[(size_t)NW*C];     // cur_feature per walker
__device__ float g_pref[(size_t)NW*C];     // pre_feature per walker
__device__ int   g_curidx[NW];             // current node index per walker
__device__ float g_S[BN*2*CN];             // softmax(mlog) values, flat (b, o*512+n)

// ---------------- transpose x (b,c,tot) -> xT (b,tot,c) ----------------
__global__ void transpose_x_kernel(const float* __restrict__ x) {
    __shared__ float tile[32][33];
    int b = blockIdx.z;
    int node0 = blockIdx.x * 32;
    int ch0 = blockIdx.y * 32;
    int tx = threadIdx.x, ty = threadIdx.y;   // 32 x 8
    const float* xb = x + (size_t)b * C * TOT;
    #pragma unroll
    for (int i = 0; i < 32; i += 8)
        tile[ty + i][tx] = xb[(size_t)(ch0 + ty + i) * TOT + node0 + tx];
    __syncthreads();
    float* xTb = g_xT + (size_t)b * TOT * C;
    #pragma unroll
    for (int i = 0; i < 32; i += 8)
        xTb[(size_t)(node0 + ty + i) * C + ch0 + tx] = tile[tx][ty + i];
}

__device__ __forceinline__ float dot8(const float4& a0, const float4& a1,
                                      const float4& b0, const float4& b1) {
    return a0.x*b0.x + a0.y*b0.y + a0.z*b0.z + a0.w*b0.w
         + a1.x*b1.x + a1.y*b1.y + a1.z*b1.z + a1.w*b1.w;
}

// ---------------- one walk step ----------------
// 8 lanes per walker, 4 walkers per warp. Lane `sub` (0..7) owns channels
// [4*sub..4*sub+3] and [32+4*sub..32+4*sub+3].
template<bool FIRST>
__global__ __launch_bounds__(256)
void walk_step_kernel(
    const int* __restrict__ adj, const int* __restrict__ cur0,
    const float* __restrict__ agent_w,
    const float* __restrict__ agent_gamma, const float* __restrict__ agent_beta,
    const float* __restrict__ agent_mean,  const float* __restrict__ agent_var,
    const float* __restrict__ mom_w,
    const float* __restrict__ mom_gamma, const float* __restrict__ mom_beta,
    const float* __restrict__ mom_mean,  const float* __restrict__ mom_var,
    float* __restrict__ out, int step)
{
    int tid = blockIdx.x * 256 + threadIdx.x;
    int w = tid >> 3;                 // walker id (0..8191)
    int sub = threadIdx.x & 7;        // lane within walker group
    int b = w >> 9;
    int n = w & 511;

    const float4* wv = (const float4*)agent_w;   // 128 floats = 32 float4
    float4 wlA = wv[sub],      wlB = wv[8 + sub];     // agent_w[0:64]
    float4 whA = wv[16 + sub], whB = wv[24 + sub];    // agent_w[64:128]

    float4 cfA, cfB, pfA, pfB, cvA, cvB;
    int cidx;

    if (FIRST) {
        cidx = __ldg(&cur0[w]);
        const float4* pv = (const float4*)(g_xT + ((size_t)b * TOT + cidx) * C);
        pfA = __ldg(&pv[sub]); pfB = __ldg(&pv[8 + sub]);
        cfA = make_float4(0.f, 0.f, 0.f, 0.f); cfB = cfA;
        cvA = cfA; cvB = cfA;
    } else {
        cidx = g_curidx[w];
        const float4* cf = (const float4*)(g_curf + (size_t)w * C);
        cfA = cf[sub]; cfB = cf[8 + sub];
        const float4* pf = (const float4*)(g_pref + (size_t)w * C);
        pfA = pf[sub]; pfB = pf[8 + sub];
        // att scramble: walker n uses flat softmax entries 2n and 2n+1
        float a0 = g_S[b * 1024 + 2 * n];
        float a1 = g_S[b * 1024 + 2 * n + 1];
        pfA.x = cfA.x*a0 + pfA.x*a1;  pfA.y = cfA.y*a0 + pfA.y*a1;
        pfA.z = cfA.z*a0 + pfA.z*a1;  pfA.w = cfA.w*a0 + pfA.w*a1;
        pfB.x = cfB.x*a0 + pfB.x*a1;  pfB.y = cfB.y*a0 + pfB.y*a1;
        pfB.z = cfB.z*a0 + pfB.z*a1;  pfB.w = cfB.w*a0 + pfB.w*a1;
        // cur_vec = cur_feature_prev - pre_feature_new
        cvA.x = cfA.x - pfA.x; cvA.y = cfA.y - pfA.y;
        cvA.z = cfA.z - pfA.z; cvA.w = cfA.w - pfA.w;
        cvB.x = cfB.x - pfB.x; cvB.y = cfB.y - pfB.y;
        cvB.z = cfB.z - pfB.z; cvB.w = cfB.w - pfB.w;
    }

    // per-lane scalar partials
    float tpp = dot8(pfA, pfB, whA, whB);               // dot(pre, w_hi)
    float n1p = FIRST ? 0.f : dot8(cvA, cvB, cvA, cvB); // |cur_vec|^2

    const int* adjp = adj + ((size_t)b * TOT + cidx) * K;

    float acc[K], cc[K], nn2[K];
    #pragma unroll
    for (int k = 0; k < K; k++) {
        int idx = __ldg(&adjp[k]);
        const float4* pv = (const float4*)(g_xT + ((size_t)b * TOT + idx) * C);
        float4 pA = __ldg(&pv[sub]);
        float4 pB = __ldg(&pv[8 + sub]);
        acc[k] = dot8(pA, pB, wlA, wlB);
        if (!FIRST) {
            float d0 = pA.x - cfA.x, d1 = pA.y - cfA.y, d2 = pA.z - cfA.z, d3 = pA.w - cfA.w;
            float d4 = pB.x - cfB.x, d5 = pB.y - cfB.y, d6 = pB.z - cfB.z, d7 = pB.w - cfB.w;
            cc[k]  = cvA.x*d0 + cvA.y*d1 + cvA.z*d2 + cvA.w*d3
                   + cvB.x*d4 + cvB.y*d5 + cvB.z*d6 + cvB.w*d7;
            nn2[k] = d0*d0 + d1*d1 + d2*d2 + d3*d3 + d4*d4 + d5*d5 + d6*d6 + d7*d7;
        }
    }

    // butterfly reduction over the 8-lane group (offsets 1,2,4 stay in-group)
    #pragma unroll
    for (int off = 1; off <= 4; off <<= 1) {
        tpp += __shfl_xor_sync(0xffffffffu, tpp, off);
        if (!FIRST) n1p += __shfl_xor_sync(0xffffffffu, n1p, off);
        #pragma unroll
        for (int k = 0; k < K; k++) {
            acc[k] += __shfl_xor_sync(0xffffffffu, acc[k], off);
            if (!FIRST) {
                cc[k]  += __shfl_xor_sync(0xffffffffu, cc[k], off);
                nn2[k] += __shfl_xor_sync(0xffffffffu, nn2[k], off);
            }
        }
    }

    float inv_a  = __ldg(agent_gamma) / sqrtf(__ldg(agent_var) + BN_EPS);
    float mean_a = __ldg(agent_mean);
    float beta_a = __ldg(agent_beta);
    float n1 = sqrtf(n1p);

    // logits + argmax (group-redundant; first-max tie break via strict >)
    float best = -3.4e38f; int ksel = 0;
    #pragma unroll
    for (int k = 0; k < K; k++) {
        float lg = (acc[k] + tpp - mean_a) * inv_a + beta_a;
        if (!FIRST) {
            float cosv = cc[k] / fmaxf(n1 * sqrtf(nn2[k]), 1e-8f);
            float d = fminf(fmaxf(1.f + cosv, 0.f), 1.f);
            lg *= d;
        }
        if (lg > best) { best = lg; ksel = k; }
    }

    int nidx = __ldg(&adjp[ksel]);
    {
        const float4* pv = (const float4*)(g_xT + ((size_t)b * TOT + nidx) * C);
        cfA = __ldg(&pv[sub]); cfB = __ldg(&pv[8 + sub]);
    }

    // write output slice: out[b][ch][n][step]
    {
        float* op = out + (size_t)b * C * CN * STEPS + (size_t)n * STEPS + step;
        int chA = sub * 4, chB = 32 + sub * 4;
        op[(size_t)(chA + 0) * (CN*STEPS)] = cfA.x;
        op[(size_t)(chA + 1) * (CN*STEPS)] = cfA.y;
        op[(size_t)(chA + 2) * (CN*STEPS)] = cfA.z;
        op[(size_t)(chA + 3) * (CN*STEPS)] = cfA.w;
        op[(size_t)(chB + 0) * (CN*STEPS)] = cfB.x;
        op[(size_t)(chB + 1) * (CN*STEPS)] = cfB.y;
        op[(size_t)(chB + 2) * (CN*STEPS)] = cfB.z;
        op[(size_t)(chB + 3) * (CN*STEPS)] = cfB.w;
    }

    // persist state
    {
        float4* cfo = (float4*)(g_curf + (size_t)w * C);
        cfo[sub] = cfA; cfo[8 + sub] = cfB;
        float4* pfo = (float4*)(g_pref + (size_t)w * C);
        pfo[sub] = pfA; pfo[8 + sub] = pfB;
        if (sub == 0) g_curidx[w] = nidx;
    }

    // mlog tail for next step: mlog = mom_w @ [cur_feature; pre_feature]
    if (step < STEPS - 1) {
        const float4* mv = (const float4*)mom_w;   // 2 rows x 32 float4
        float l0 = dot8(cfA, cfB, mv[sub],      mv[8 + sub])
                 + dot8(pfA, pfB, mv[16 + sub], mv[24 + sub]);
        float l1 = dot8(cfA, cfB, mv[32 + sub], mv[40 + sub])
                 + dot8(pfA, pfB, mv[48 + sub], mv[56 + sub]);
        #pragma unroll
        for (int off = 1; off <= 4; off <<= 1) {
            l0 += __shfl_xor_sync(0xffffffffu, l0, off);
            l1 += __shfl_xor_sync(0xffffffffu, l1, off);
        }
        if (sub == 0) {
            float inv0 = __ldg(&mom_gamma[0]) / sqrtf(__ldg(&mom_var[0]) + BN_EPS);
            float inv1 = __ldg(&mom_gamma[1]) / sqrtf(__ldg(&mom_var[1]) + BN_EPS);
            l0 = (l0 - __ldg(&mom_mean[0])) * inv0 + __ldg(&mom_beta[0]);
            l1 = (l1 - __ldg(&mom_mean[1])) * inv1 + __ldg(&mom_beta[1]);
            float mx = fmaxf(l0, l1);
            float e0 = expf(l0 - mx), e1 = expf(l1 - mx);
            float s = e0 + e1;
            g_S[b * 1024 + n]       = e0 / s;
            g_S[b * 1024 + 512 + n] = e1 / s;
        }
    }
}

extern "C" void kernel_launch(void* const* d_in, const int* in_sizes, int n_in,
                              void* d_out, int out_size) {
    const float* x          = (const float*)d_in[1];
    const int*   adj        = (const int*)  d_in[2];
    const int*   cur        = (const int*)  d_in[3];
    const float* agent_w    = (const float*)d_in[4];
    const float* agent_gamma= (const float*)d_in[5];
    const float* agent_beta = (const float*)d_in[6];
    const float* agent_mean = (const float*)d_in[7];
    const float* agent_var  = (const float*)d_in[8];
    const float* mom_w      = (const float*)d_in[9];
    const float* mom_gamma  = (const float*)d_in[10];
    const float* mom_beta   = (const float*)d_in[11];
    const float* mom_mean   = (const float*)d_in[12];
    const float* mom_var    = (const float*)d_in[13];
    float* out = (float*)d_out;

    dim3 tb(32, 8), tg(TOT / 32, C / 32, BN);
    transpose_x_kernel<<<tg, tb>>>(x);

    int blocks = (NW * 8) / 256;   // 256 blocks of 256 threads
    walk_step_kernel<true><<<blocks, 256>>>(adj, cur, agent_w, agent_gamma,
        agent_beta, agent_mean, agent_var, mom_w, mom_gamma, mom_beta,
        mom_mean, mom_var, out, 0);
    for (int s = 1; s < STEPS; s++) {
        walk_step_kernel<false><<<blocks, 256>>>(adj, cur, agent_w, agent_gamma,
            agent_beta, agent_mean, agent_var, mom_w, mom_gamma, mom_beta,
            mom_mean, mom_var, out, s);
    }
}